// round 1
// baseline (speedup 1.0000x reference)
#include <cuda_runtime.h>
#include <cuda_bf16.h>
#include <math.h>

// ---------------- problem constants ----------------
#define BQ 2
#define LSEQ 4096
#define DMODEL 1024
#define DINNER 2048
#define NH 32
#define HD 64
#define DSTATE 128
#define CHK 64           // chunk length
#define NC 64            // number of chunks (4096/64)
#define DPROJ 4384       // 2*DINNER + 2*DSTATE + NH
#define CONVCH 2304      // DINNER + 2*DSTATE
#define MROWS (BQ*LSEQ)  // 8192

// ---------------- scratch (device globals; no allocation) ----------------
__device__ float g_zx[(size_t)MROWS * DPROJ];            // in_proj output  (~144MB)
__device__ float g_xbc[(size_t)MROWS * CONVCH];          // conv+silu output (~75MB)
__device__ float g_dt[MROWS * NH];                       // softplus(dt)
__device__ float g_acum[BQ * NC * NH * CHK];             // intra-chunk cumsum of A*dt
__device__ float g_suma[BQ * NC * NH];                   // per-chunk sum of A*dt
__device__ float g_states[(size_t)BQ * NC * NH * HD * DSTATE]; // chunk states (~128MB)
__device__ float g_y[(size_t)MROWS * DINNER];            // y buffer (~64MB)

// ---------------- generic fp32 SGEMM: C = A(MxK) * B(KxN) ----------------
__global__ void sgemm_kernel(const float* __restrict__ A, const float* __restrict__ B,
                             float* __restrict__ C, int M, int N, int K) {
    __shared__ float As[16][136];  // [BK][BM+8] : float4-aligned fragments
    __shared__ float Bs[16][136];  // [BK][BN+8]
    const int tid  = threadIdx.x;          // 256 threads
    const int trow = tid >> 4;             // 0..15
    const int tcol = tid & 15;             // 0..15
    const int rowbase = blockIdx.y * 128;
    const int colbase = blockIdx.x * 128;
    float acc[8][8];
#pragma unroll
    for (int i = 0; i < 8; i++)
#pragma unroll
        for (int j = 0; j < 8; j++) acc[i][j] = 0.f;

    for (int k0 = 0; k0 < K; k0 += 16) {
#pragma unroll
        for (int j = 0; j < 8; j++) {          // A tile: 128x16
            int i = tid + 256 * j;
            int r = i >> 4, c = i & 15;
            int gr = rowbase + r, gc = k0 + c;
            As[c][r] = (gr < M && gc < K) ? A[(size_t)gr * K + gc] : 0.f;
        }
#pragma unroll
        for (int j = 0; j < 8; j++) {          // B tile: 16x128
            int i = tid + 256 * j;
            int r = i >> 7, c = i & 127;
            int gr = k0 + r, gc = colbase + c;
            Bs[r][c] = (gr < K && gc < N) ? B[(size_t)gr * N + gc] : 0.f;
        }
        __syncthreads();
#pragma unroll
        for (int kk = 0; kk < 16; kk++) {
            float4 a0 = *reinterpret_cast<const float4*>(&As[kk][trow * 8]);
            float4 a1 = *reinterpret_cast<const float4*>(&As[kk][trow * 8 + 4]);
            float4 b0 = *reinterpret_cast<const float4*>(&Bs[kk][tcol * 8]);
            float4 b1 = *reinterpret_cast<const float4*>(&Bs[kk][tcol * 8 + 4]);
            float a[8] = {a0.x, a0.y, a0.z, a0.w, a1.x, a1.y, a1.z, a1.w};
            float b[8] = {b0.x, b0.y, b0.z, b0.w, b1.x, b1.y, b1.z, b1.w};
#pragma unroll
            for (int i = 0; i < 8; i++)
#pragma unroll
                for (int j = 0; j < 8; j++) acc[i][j] = fmaf(a[i], b[j], acc[i][j]);
        }
        __syncthreads();
    }
#pragma unroll
    for (int i = 0; i < 8; i++) {
        int gr = rowbase + trow * 8 + i;
        if (gr >= M) continue;
#pragma unroll
        for (int j = 0; j < 8; j++) {
            int gc = colbase + tcol * 8 + j;
            if (gc < N) C[(size_t)gr * N + gc] = acc[i][j];
        }
    }
}

// ---------------- dt = softplus(raw + bias) ----------------
__global__ void dt_kernel(const float* __restrict__ dt_bias) {
    int idx = blockIdx.x * blockDim.x + threadIdx.x;  // MROWS*NH
    int h = idx & 31;
    int m = idx >> 5;
    float x = g_zx[(size_t)m * DPROJ + (DPROJ - NH) + h] + dt_bias[h];
    g_dt[idx] = (x > 20.f) ? x : log1pf(expf(x));
}

// ---------------- per (b,c,h): cumsum of A*dt over chunk ----------------
__global__ void acum_kernel(const float* __restrict__ A_log) {
    int idx = blockIdx.x * blockDim.x + threadIdx.x;  // BQ*NC*NH = 4096
    if (idx >= BQ * NC * NH) return;
    int h = idx & 31;
    int c = (idx >> 5) & 63;
    int b = idx >> 11;
    float A = -expf(A_log[h]);
    int m0 = b * LSEQ + c * CHK;
    float cum = 0.f;
    for (int l = 0; l < CHK; l++) {
        cum += A * g_dt[(m0 + l) * NH + h];
        g_acum[idx * CHK + l] = cum;
    }
    g_suma[idx] = cum;
}

// ---------------- depthwise causal conv(4) + bias + SiLU ----------------
__global__ void conv_kernel(const float* __restrict__ cw, const float* __restrict__ cb) {
    int ch = blockIdx.x * blockDim.x + threadIdx.x;
    int m = blockIdx.y;   // 0..MROWS-1
    if (ch >= CONVCH) return;
    int l = m & (LSEQ - 1);
    float acc = cb[ch];
#pragma unroll
    for (int k = 0; k < 4; k++) {
        int l2 = l - 3 + k;
        if (l2 >= 0)
            acc = fmaf(g_zx[(size_t)(m - 3 + k) * DPROJ + DINNER + ch], cw[ch * 4 + k], acc);
    }
    g_xbc[(size_t)m * CONVCH + ch] = acc / (1.f + expf(-acc));
}

// ---------------- SSD intra-chunk: Y_diag + local states ----------------
// one block per (b, c, h); smem strides 129 / 65 are conflict-free
__global__ void ssd_diag_kernel() {
    int blk = blockIdx.x;            // b*2048 + c*32 + h
    int h = blk & 31;
    int c = (blk >> 5) & 63;
    int b = blk >> 11;
    int m0 = b * LSEQ + c * CHK;

    extern __shared__ float sm[];
    float* Bs = sm;                  // 64*129
    float* Cs = Bs + 64 * 129;       // 64*129
    float* xs = Cs + 64 * 129;       // 64*65
    float* Gs = xs + 64 * 65;        // 64*65
    float* ac = Gs + 64 * 65;        // 64
    float* wd = ac + 64;             // 64
    int tid = threadIdx.x;

    for (int i = tid; i < 64 * 128; i += 256) {
        int l = i >> 7, n = i & 127;
        size_t base = (size_t)(m0 + l) * CONVCH;
        Bs[l * 129 + n] = g_xbc[base + DINNER + n];
        Cs[l * 129 + n] = g_xbc[base + DINNER + DSTATE + n];
    }
    for (int i = tid; i < 64 * 64; i += 256) {
        int l = i >> 6, p = i & 63;
        xs[l * 65 + p] = g_xbc[(size_t)(m0 + l) * CONVCH + h * HD + p] * g_dt[(m0 + l) * NH + h];
    }
    if (tid < 64) ac[tid] = g_acum[blk * CHK + tid];
    __syncthreads();
    if (tid < 64) wd[tid] = expf(ac[63] - ac[tid]);

    // G[l][s] = C[l]·B[s], then apply segsum decay mask in place
#pragma unroll
    for (int t = 0; t < 16; t++) {
        int e = t * 256 + tid;
        int l = e >> 6, s = e & 63;
        float acc = 0.f;
#pragma unroll 16
        for (int n = 0; n < 128; n++) acc = fmaf(Cs[l * 129 + n], Bs[s * 129 + n], acc);
        Gs[l * 65 + s] = (s <= l) ? acc * expf(ac[l] - ac[s]) : 0.f;
    }
    __syncthreads();

    // Y_diag[l][p] = sum_s M[l][s] * xdt[s][p]
#pragma unroll
    for (int t = 0; t < 16; t++) {
        int e = t * 256 + tid;
        int l = e >> 6, p = e & 63;
        float acc = 0.f;
#pragma unroll 16
        for (int s = 0; s < 64; s++) acc = fmaf(Gs[l * 65 + s], xs[s * 65 + p], acc);
        g_y[(size_t)(m0 + l) * DINNER + h * HD + p] = acc;
    }

    // local state S[p][n] = sum_l w[l] * xdt[l][p] * B[l][n]
#pragma unroll
    for (int t = 0; t < 32; t++) {
        int e = t * 256 + tid;
        int p = e >> 7, n = e & 127;
        float acc = 0.f;
#pragma unroll 16
        for (int l = 0; l < 64; l++) acc = fmaf(wd[l] * xs[l * 65 + p], Bs[l * 129 + n], acc);
        g_states[((size_t)blk * HD + p) * DSTATE + n] = acc;
    }
}

// ---------------- inter-chunk scan (in-place: states[c] becomes state ENTERING chunk c) ----
__global__ void scan_kernel() {
    int idx = blockIdx.x * blockDim.x + threadIdx.x;  // BQ*NH*HD*DSTATE = 524288
    int n = idx & 127;
    int p = (idx >> 7) & 63;
    int h = (idx >> 13) & 31;
    int b = idx >> 18;
    float prev = 0.f;
    for (int c = 0; c < NC; c++) {
        int bch = (b * NC + c) * NH + h;
        size_t off = ((size_t)bch * HD + p) * DSTATE + n;
        float loc = g_states[off];
        g_states[off] = prev;
        prev = fmaf(prev, expf(g_suma[bch]), loc);
    }
}

// ---------------- Y_off + skip term: y += exp(acum)·(C·P) + x*D ----------------
__global__ void yoff_kernel(const float* __restrict__ Dv) {
    int blk = blockIdx.x;
    int h = blk & 31;
    int c = (blk >> 5) & 63;
    int b = blk >> 11;
    int m0 = b * LSEQ + c * CHK;

    extern __shared__ float sm[];
    float* Ps = sm;                  // 64*129 (p x n)
    float* Cs = Ps + 64 * 129;       // 64*129 (l x n)
    float* ac = Cs + 64 * 129;       // 64
    int tid = threadIdx.x;

    for (int i = tid; i < 64 * 128; i += 256) {
        int p = i >> 7, n = i & 127;
        Ps[p * 129 + n] = g_states[((size_t)blk * HD + p) * DSTATE + n];
    }
    for (int i = tid; i < 64 * 128; i += 256) {
        int l = i >> 7, n = i & 127;
        Cs[l * 129 + n] = g_xbc[(size_t)(m0 + l) * CONVCH + DINNER + DSTATE + n];
    }
    if (tid < 64) ac[tid] = g_acum[blk * CHK + tid];
    float Dh = Dv[h];
    __syncthreads();

#pragma unroll
    for (int t = 0; t < 16; t++) {
        int e = t * 256 + tid;
        int l = e >> 6, p = e & 63;
        float acc = 0.f;
#pragma unroll 16
        for (int n = 0; n < 128; n++) acc = fmaf(Cs[l * 129 + n], Ps[p * 129 + n], acc);
        size_t yi = (size_t)(m0 + l) * DINNER + h * HD + p;
        float xv = g_xbc[(size_t)(m0 + l) * CONVCH + h * HD + p];
        g_y[yi] += acc * expf(ac[l]) + xv * Dh;
    }
}

// ---------------- gate (silu(z)) + RMSNorm, in place in g_y ----------------
__global__ void gate_kernel(const float* __restrict__ norm_w) {
    int m = blockIdx.x;
    int tid = threadIdx.x;
    __shared__ float red[256];
    float tv[8];
    float ss = 0.f;
#pragma unroll
    for (int j = 0; j < 8; j++) {
        int i = tid + 256 * j;
        float zv = g_zx[(size_t)m * DPROJ + i];
        float yv = g_y[(size_t)m * DINNER + i];
        float g = yv * (zv / (1.f + expf(-zv)));
        tv[j] = g;
        ss += g * g;
    }
    red[tid] = ss;
    __syncthreads();
    for (int s = 128; s > 0; s >>= 1) {
        if (tid < s) red[tid] += red[tid + s];
        __syncthreads();
    }
    float scale = rsqrtf(red[0] / (float)DINNER + 1e-5f);
#pragma unroll
    for (int j = 0; j < 8; j++) {
        int i = tid + 256 * j;
        g_y[(size_t)m * DINNER + i] = tv[j] * scale * norm_w[i];
    }
}

// ---------------- launch ----------------
extern "C" void kernel_launch(void* const* d_in, const int* in_sizes, int n_in,
                              void* d_out, int out_size) {
    const float* u      = (const float*)d_in[0];
    const float* W_in   = (const float*)d_in[1];
    const float* conv_w = (const float*)d_in[2];
    const float* conv_b = (const float*)d_in[3];
    const float* dt_b   = (const float*)d_in[4];
    const float* A_log  = (const float*)d_in[5];
    const float* Dv     = (const float*)d_in[6];
    const float* norm_w = (const float*)d_in[7];
    const float* W_out  = (const float*)d_in[8];
    float* out = (float*)d_out;

    float *zx = nullptr, *ybuf = nullptr;
    cudaGetSymbolAddress((void**)&zx, g_zx);
    cudaGetSymbolAddress((void**)&ybuf, g_y);

    const size_t diag_smem = (size_t)(2 * 64 * 129 + 2 * 64 * 65 + 128) * sizeof(float);  // 99840 B
    const size_t yoff_smem = (size_t)(2 * 64 * 129 + 64) * sizeof(float);                 // 66304 B
    cudaFuncSetAttribute(ssd_diag_kernel, cudaFuncAttributeMaxDynamicSharedMemorySize, (int)diag_smem);
    cudaFuncSetAttribute(yoff_kernel, cudaFuncAttributeMaxDynamicSharedMemorySize, (int)yoff_smem);

    // 1) in_proj GEMM: (8192x1024) @ (1024x4384)
    dim3 g1((DPROJ + 127) / 128, MROWS / 128);
    sgemm_kernel<<<g1, 256>>>(u, W_in, zx, MROWS, DPROJ, DMODEL);

    // 2) dt softplus + 3) cumsum A*dt
    dt_kernel<<<MROWS * NH / 256, 256>>>(dt_b);
    acum_kernel<<<BQ * NC * NH / 256, 256>>>(A_log);

    // 4) depthwise conv + silu
    conv_kernel<<<dim3(CONVCH / 256, MROWS), 256>>>(conv_w, conv_b);

    // 5) SSD intra-chunk (Y_diag + local states)
    ssd_diag_kernel<<<BQ * NC * NH, 256, diag_smem>>>();

    // 6) inter-chunk scan
    scan_kernel<<<(BQ * NH * HD * DSTATE) / 256, 256>>>();

    // 7) Y_off + x*D
    yoff_kernel<<<BQ * NC * NH, 256, yoff_smem>>>(Dv);

    // 8) gate + rmsnorm
    gate_kernel<<<MROWS, 256>>>(norm_w);

    // 9) out_proj GEMM: (8192x2048) @ (2048x1024)
    dim3 g2(DMODEL / 128, MROWS / 128);
    sgemm_kernel<<<g2, 256>>>(ybuf, W_out, out, MROWS, DMODEL, DINNER);
}

// round 4
// speedup vs baseline: 1.5281x; 1.5281x over previous
#include <cuda_runtime.h>
#include <cuda_bf16.h>
#include <math.h>
#include <cstdint>

// ---------------- problem constants ----------------
#define BQ 2
#define LSEQ 4096
#define DMODEL 1024
#define DINNER 2048
#define NH 32
#define HD 64
#define DSTATE 128
#define CHK 64
#define NC 64
#define DPROJ 4384
#define CONVCH 2304
#define MROWS (BQ*LSEQ)
#define NPAD1 4480      // DPROJ padded to 128

// ---------------- scratch (device globals; no allocation) ----------------
__device__ float g_zx[(size_t)MROWS * DPROJ];
__device__ float g_xbc[(size_t)MROWS * CONVCH];
__device__ float g_dt[MROWS * NH];
__device__ float g_acum[BQ * NC * NH * CHK];
__device__ float g_suma[BQ * NC * NH];              // exp(sum A*dt) per chunk
__device__ float g_states[(size_t)BQ * NC * NH * HD * DSTATE];
__device__ float g_y[(size_t)MROWS * DINNER];

// bf16 split buffers for tensor-core GEMMs
__device__ __nv_bfloat16 g_a1h[(size_t)MROWS * DMODEL];
__device__ __nv_bfloat16 g_a1l[(size_t)MROWS * DMODEL];
__device__ __nv_bfloat16 g_b1h[(size_t)NPAD1 * DMODEL];
__device__ __nv_bfloat16 g_b1l[(size_t)NPAD1 * DMODEL];
__device__ __nv_bfloat16 g_a2h[(size_t)MROWS * DINNER];
__device__ __nv_bfloat16 g_a2l[(size_t)MROWS * DINNER];
__device__ __nv_bfloat16 g_b2h[(size_t)DMODEL * DINNER];
__device__ __nv_bfloat16 g_b2l[(size_t)DMODEL * DINNER];

// ---------------- PTX helpers (base ISA only: no tcgen05 on this target) ----------------
__device__ __forceinline__ uint32_t smem_u32(const void* p) {
    uint32_t a;
    asm("{ .reg .u64 t; cvta.to.shared.u64 t, %1; cvt.u32.u64 %0, t; }" : "=r"(a) : "l"(p));
    return a;
}
#define SMEM_SWIZZLE_128B(byte_offset) ((byte_offset) ^ (((byte_offset) >> 3) & 0x70))
#define CP_ASYNC16(dst, src) \
    asm volatile("cp.async.cg.shared.global [%0], [%1], 16;" :: "r"(dst), "l"(src) : "memory")
#define CP_COMMIT() asm volatile("cp.async.commit_group;" ::: "memory")
#define CP_WAIT0()  asm volatile("cp.async.wait_group 0;" ::: "memory")

#define LDSM_X4(r0,r1,r2,r3,addr) \
    asm volatile("ldmatrix.sync.aligned.m8n8.x4.shared.b16 {%0,%1,%2,%3}, [%4];" \
        : "=r"(r0), "=r"(r1), "=r"(r2), "=r"(r3) : "r"(addr))

#define MMA16816(d, a, b0, b1) \
    asm volatile("mma.sync.aligned.m16n8k16.row.col.f32.bf16.bf16.f32 " \
        "{%0,%1,%2,%3}, {%4,%5,%6,%7}, {%8,%9}, {%0,%1,%2,%3};" \
        : "+f"((d)[0]), "+f"((d)[1]), "+f"((d)[2]), "+f"((d)[3]) \
        : "r"((a)[0]), "r"((a)[1]), "r"((a)[2]), "r"((a)[3]), "r"(b0), "r"(b1))

// A fragment load: 16x16 bf16 atom at (row128 .. +15, ks*16 .. +15) of a 128x64 tile
__device__ __forceinline__ void ldsmA(uint32_t base, int row128, int ks, int lane, uint32_t* r) {
    int row = row128 + (lane & 15);
    int off = row * 128 + ks * 32 + ((lane >> 4) << 4);
    LDSM_X4(r[0], r[1], r[2], r[3], base + SMEM_SWIZZLE_128B((uint32_t)off));
}
// B fragment load (NON-trans: Bt stored [n][k] k-contiguous gives col-major B frags):
// lanes 0-7: n=nrow+0..7 k0-7 (-> b0 of n-block0), lanes 8-15: same n, k8-15 (-> b1),
// lanes 16-23/24-31: n-block1.
__device__ __forceinline__ void ldsmB(uint32_t base, int nrow, int ks, int lane, uint32_t* r) {
    int n = nrow + ((lane >> 4) << 3) + (lane & 7);
    int off = n * 128 + ks * 32 + (((lane >> 3) & 1) << 4);
    LDSM_X4(r[0], r[1], r[2], r[3], base + SMEM_SWIZZLE_128B((uint32_t)off));
}

// ---------------- HMMA split-bf16 GEMM: C[M,N] = A[M,K] @ Bt[N,K]^T ----------------
// CTA tile 128x128, K-chunk 64 bf16, double-buffered cp.async, 8 warps of 64x32.
// 3 products accumulated: Ah*Bh + Ah*Bl + Al*Bh.
__global__ __launch_bounds__(256, 1) void hmma_gemm_kernel(
    const __nv_bfloat16* __restrict__ Ah, const __nv_bfloat16* __restrict__ Al,
    const __nv_bfloat16* __restrict__ Bh, const __nv_bfloat16* __restrict__ Bl,
    float* __restrict__ C, int N, int K, int ldc)
{
    extern __shared__ char smem[];
    const uint32_t sb = smem_u32(smem);
    const int tid = threadIdx.x, wid = tid >> 5, lane = tid & 31;
    const int wr = wid & 1, wc = wid >> 1;          // warp tile: rows wr*64, cols wc*32
    const int rowbase = blockIdx.y * 128, colbase = blockIdx.x * 128;
    const int KC = K >> 6;

    float acc[4][4][4];
#pragma unroll
    for (int mi = 0; mi < 4; mi++)
#pragma unroll
        for (int ni = 0; ni < 4; ni++)
#pragma unroll
            for (int j = 0; j < 4; j++) acc[mi][ni][j] = 0.f;

    auto issue_chunk = [&](int i) {
        const uint32_t sbase = (uint32_t)(i & 1) * 65536u;
        const int k0 = i << 6;
#pragma unroll
        for (int v = 0; v < 16; v++) {
            const int buf = v >> 2;                 // 0:Ah 1:Al 2:Bh 3:Bl
            const int idx = ((v & 3) << 8) + tid;   // 0..1023 -> 16KB per buf
            const int r = idx >> 3, c8 = idx & 7;
            const __nv_bfloat16* src;
            if (buf == 0)      src = Ah + (size_t)(rowbase + r) * K + k0 + c8 * 8;
            else if (buf == 1) src = Al + (size_t)(rowbase + r) * K + k0 + c8 * 8;
            else if (buf == 2) src = Bh + (size_t)(colbase + r) * K + k0 + c8 * 8;
            else               src = Bl + (size_t)(colbase + r) * K + k0 + c8 * 8;
            uint32_t dst = sb + sbase + (uint32_t)buf * 16384u +
                           SMEM_SWIZZLE_128B((uint32_t)(r * 128 + c8 * 16));
            CP_ASYNC16(dst, src);
        }
    };

    issue_chunk(0);
    CP_COMMIT();

    for (int i = 0; i < KC; i++) {
        CP_WAIT0();
        __syncthreads();
        if (i + 1 < KC) { issue_chunk(i + 1); CP_COMMIT(); }

        const uint32_t sbase = sb + (uint32_t)(i & 1) * 65536u;
        const uint32_t aH = sbase, aL = sbase + 16384u, bH = sbase + 32768u, bL = sbase + 49152u;
#pragma unroll
        for (int ks = 0; ks < 4; ks++) {
            uint32_t ah[4][4], al[4][4], bh[2][4], bl[2][4];
#pragma unroll
            for (int mi = 0; mi < 4; mi++) {
                ldsmA(aH, wr * 64 + mi * 16, ks, lane, ah[mi]);
                ldsmA(aL, wr * 64 + mi * 16, ks, lane, al[mi]);
            }
#pragma unroll
            for (int np = 0; np < 2; np++) {
                ldsmB(bH, wc * 32 + np * 16, ks, lane, bh[np]);
                ldsmB(bL, wc * 32 + np * 16, ks, lane, bl[np]);
            }
#pragma unroll
            for (int mi = 0; mi < 4; mi++)
#pragma unroll
                for (int ni = 0; ni < 4; ni++) {
                    const int np = ni >> 1, o = (ni & 1) << 1;
                    MMA16816(acc[mi][ni], ah[mi], bh[np][o], bh[np][o + 1]);
                    MMA16816(acc[mi][ni], ah[mi], bl[np][o], bl[np][o + 1]);
                    MMA16816(acc[mi][ni], al[mi], bh[np][o], bh[np][o + 1]);
                }
        }
        __syncthreads();
    }

    // epilogue: m16n8 D layout -> C
#pragma unroll
    for (int mi = 0; mi < 4; mi++) {
        const int row = rowbase + wr * 64 + mi * 16 + (lane >> 2);
#pragma unroll
        for (int ni = 0; ni < 4; ni++) {
            const int col = colbase + wc * 32 + ni * 8 + (lane & 3) * 2;
            if (col < N) {
                *reinterpret_cast<float2*>(&C[(size_t)row * ldc + col]) =
                    make_float2(acc[mi][ni][0], acc[mi][ni][1]);
                *reinterpret_cast<float2*>(&C[(size_t)(row + 8) * ldc + col]) =
                    make_float2(acc[mi][ni][2], acc[mi][ni][3]);
            }
        }
    }
}

// ---------------- fp32 -> (hi, lo) bf16 split ----------------
__global__ void cvt_split_kernel(const float* __restrict__ X, __nv_bfloat16* __restrict__ hi,
                                 __nv_bfloat16* __restrict__ lo, int n4) {
    int i = blockIdx.x * blockDim.x + threadIdx.x;
    if (i >= n4) return;
    float4 x = reinterpret_cast<const float4*>(X)[i];
    float xs[4] = {x.x, x.y, x.z, x.w};
    __nv_bfloat16 h[4], l[4];
#pragma unroll
    for (int j = 0; j < 4; j++) {
        h[j] = __float2bfloat16(xs[j]);
        l[j] = __float2bfloat16(xs[j] - __bfloat162float(h[j]));
    }
    reinterpret_cast<__nv_bfloat162*>(hi)[2 * i]     = __nv_bfloat162(h[0], h[1]);
    reinterpret_cast<__nv_bfloat162*>(hi)[2 * i + 1] = __nv_bfloat162(h[2], h[3]);
    reinterpret_cast<__nv_bfloat162*>(lo)[2 * i]     = __nv_bfloat162(l[0], l[1]);
    reinterpret_cast<__nv_bfloat162*>(lo)[2 * i + 1] = __nv_bfloat162(l[2], l[3]);
}

// ---------------- W[K,N] -> Bt[Npad,K] (hi,lo), zero-padded ----------------
__global__ void transpose_split_kernel(const float* __restrict__ W,
                                       __nv_bfloat16* __restrict__ th,
                                       __nv_bfloat16* __restrict__ tl, int K, int N) {
    __shared__ float t[32][33];
    int n = blockIdx.x * 32 + threadIdx.x;
    int k = blockIdx.y * 32 + threadIdx.y;
    t[threadIdx.y][threadIdx.x] = (n < N) ? W[(size_t)k * N + n] : 0.f;
    __syncthreads();
    int nn = blockIdx.x * 32 + threadIdx.y;
    int kk = blockIdx.y * 32 + threadIdx.x;
    float v = t[threadIdx.x][threadIdx.y];
    __nv_bfloat16 h = __float2bfloat16(v);
    th[(size_t)nn * K + kk] = h;
    tl[(size_t)nn * K + kk] = __float2bfloat16(v - __bfloat162float(h));
}

// ---------------- dt = softplus(raw + bias) ----------------
__global__ void dt_kernel(const float* __restrict__ dt_bias) {
    int idx = blockIdx.x * blockDim.x + threadIdx.x;
    int h = idx & 31;
    int m = idx >> 5;
    float x = g_zx[(size_t)m * DPROJ + (DPROJ - NH) + h] + dt_bias[h];
    g_dt[idx] = (x > 20.f) ? x : log1pf(expf(x));
}

// ---------------- per (b,c,h): cumsum of A*dt over chunk ----------------
__global__ void acum_kernel(const float* __restrict__ A_log) {
    int idx = blockIdx.x * blockDim.x + threadIdx.x;
    if (idx >= BQ * NC * NH) return;
    int h = idx & 31;
    int c = (idx >> 5) & 63;
    int b = idx >> 11;
    float A = -expf(A_log[h]);
    int m0 = b * LSEQ + c * CHK;
    float cum = 0.f;
    for (int l = 0; l < CHK; l++) {
        cum += A * g_dt[(m0 + l) * NH + h];
        g_acum[idx * CHK + l] = cum;
    }
    g_suma[idx] = expf(cum);
}

// ---------------- depthwise causal conv(4) + bias + SiLU ----------------
__global__ void conv_kernel(const float* __restrict__ cw, const float* __restrict__ cb) {
    int ch = blockIdx.x * blockDim.x + threadIdx.x;
    int m = blockIdx.y;
    if (ch >= CONVCH) return;
    int l = m & (LSEQ - 1);
    float acc = cb[ch];
#pragma unroll
    for (int k = 0; k < 4; k++) {
        int l2 = l - 3 + k;
        if (l2 >= 0)
            acc = fmaf(g_zx[(size_t)(m - 3 + k) * DPROJ + DINNER + ch], cw[ch * 4 + k], acc);
    }
    g_xbc[(size_t)m * CONVCH + ch] = acc / (1.f + expf(-acc));
}

// ---------------- SSD intra-chunk: Y_diag + local states ----------------
__global__ void ssd_diag_kernel() {
    int blk = blockIdx.x;
    int h = blk & 31;
    int c = (blk >> 5) & 63;
    int b = blk >> 11;
    int m0 = b * LSEQ + c * CHK;

    extern __shared__ float sm[];
    float* Bs = sm;
    float* Cs = Bs + 64 * 129;
    float* xs = Cs + 64 * 129;
    float* Gs = xs + 64 * 65;
    float* ac = Gs + 64 * 65;
    float* wd = ac + 64;
    int tid = threadIdx.x;

    for (int i = tid; i < 64 * 128; i += 256) {
        int l = i >> 7, n = i & 127;
        size_t base = (size_t)(m0 + l) * CONVCH;
        Bs[l * 129 + n] = g_xbc[base + DINNER + n];
        Cs[l * 129 + n] = g_xbc[base + DINNER + DSTATE + n];
    }
    for (int i = tid; i < 64 * 64; i += 256) {
        int l = i >> 6, p = i & 63;
        xs[l * 65 + p] = g_xbc[(size_t)(m0 + l) * CONVCH + h * HD + p] * g_dt[(m0 + l) * NH + h];
    }
    if (tid < 64) ac[tid] = g_acum[blk * CHK + tid];
    __syncthreads();
    if (tid < 64) wd[tid] = expf(ac[63] - ac[tid]);

#pragma unroll
    for (int t = 0; t < 16; t++) {
        int e = t * 256 + tid;
        int l = e >> 6, s = e & 63;
        float acc = 0.f;
#pragma unroll 16
        for (int n = 0; n < 128; n++) acc = fmaf(Cs[l * 129 + n], Bs[s * 129 + n], acc);
        Gs[l * 65 + s] = (s <= l) ? acc * expf(ac[l] - ac[s]) : 0.f;
    }
    __syncthreads();

#pragma unroll
    for (int t = 0; t < 16; t++) {
        int e = t * 256 + tid;
        int l = e >> 6, p = e & 63;
        float acc = 0.f;
#pragma unroll 16
        for (int s = 0; s < 64; s++) acc = fmaf(Gs[l * 65 + s], xs[s * 65 + p], acc);
        g_y[(size_t)(m0 + l) * DINNER + h * HD + p] = acc;
    }

#pragma unroll
    for (int t = 0; t < 32; t++) {
        int e = t * 256 + tid;
        int p = e >> 7, n = e & 127;
        float acc = 0.f;
#pragma unroll 16
        for (int l = 0; l < 64; l++) acc = fmaf(wd[l] * xs[l * 65 + p], Bs[l * 129 + n], acc);
        g_states[((size_t)blk * HD + p) * DSTATE + n] = acc;
    }
}

// ---------------- inter-chunk scan ----------------
__global__ void scan_kernel() {
    int idx = blockIdx.x * blockDim.x + threadIdx.x;
    int n = idx & 127;
    int p = (idx >> 7) & 63;
    int h = (idx >> 13) & 31;
    int b = idx >> 18;
    float prev = 0.f;
    for (int c = 0; c < NC; c++) {
        int bch = (b * NC + c) * NH + h;
        size_t off = ((size_t)bch * HD + p) * DSTATE + n;
        float loc = g_states[off];
        g_states[off] = prev;
        prev = fmaf(prev, g_suma[bch], loc);
    }
}

// ---------------- Y_off + skip term ----------------
__global__ void yoff_kernel(const float* __restrict__ Dv) {
    int blk = blockIdx.x;
    int h = blk & 31;
    int c = (blk >> 5) & 63;
    int b = blk >> 11;
    int m0 = b * LSEQ + c * CHK;

    extern __shared__ float sm[];
    float* Ps = sm;
    float* Cs = Ps + 64 * 129;
    float* ac = Cs + 64 * 129;
    int tid = threadIdx.x;

    for (int i = tid; i < 64 * 128; i += 256) {
        int p = i >> 7, n = i & 127;
        Ps[p * 129 + n] = g_states[((size_t)blk * HD + p) * DSTATE + n];
    }
    for (int i = tid; i < 64 * 128; i += 256) {
        int l = i >> 7, n = i & 127;
        Cs[l * 129 + n] = g_xbc[(size_t)(m0 + l) * CONVCH + DINNER + DSTATE + n];
    }
    if (tid < 64) ac[tid] = g_acum[blk * CHK + tid];
    float Dh = Dv[h];
    __syncthreads();

#pragma unroll
    for (int t = 0; t < 16; t++) {
        int e = t * 256 + tid;
        int l = e >> 6, p = e & 63;
        float acc = 0.f;
#pragma unroll 16
        for (int n = 0; n < 128; n++) acc = fmaf(Cs[l * 129 + n], Ps[p * 129 + n], acc);
        size_t yi = (size_t)(m0 + l) * DINNER + h * HD + p;
        float xv = g_xbc[(size_t)(m0 + l) * CONVCH + h * HD + p];
        g_y[yi] += acc * expf(ac[l]) + xv * Dh;
    }
}

// ---------------- gate (silu(z)) + RMSNorm ----------------
__global__ void gate_kernel(const float* __restrict__ norm_w) {
    int m = blockIdx.x;
    int tid = threadIdx.x;
    __shared__ float red[256];
    float tv[8];
    float ss = 0.f;
#pragma unroll
    for (int j = 0; j < 8; j++) {
        int i = tid + 256 * j;
        float zv = g_zx[(size_t)m * DPROJ + i];
        float yv = g_y[(size_t)m * DINNER + i];
        float g = yv * (zv / (1.f + expf(-zv)));
        tv[j] = g;
        ss += g * g;
    }
    red[tid] = ss;
    __syncthreads();
    for (int s = 128; s > 0; s >>= 1) {
        if (tid < s) red[tid] += red[tid + s];
        __syncthreads();
    }
    float scale = rsqrtf(red[0] / (float)DINNER + 1e-5f);
#pragma unroll
    for (int j = 0; j < 8; j++) {
        int i = tid + 256 * j;
        g_y[(size_t)m * DINNER + i] = tv[j] * scale * norm_w[i];
    }
}

// ---------------- launch ----------------
extern "C" void kernel_launch(void* const* d_in, const int* in_sizes, int n_in,
                              void* d_out, int out_size) {
    const float* u      = (const float*)d_in[0];
    const float* W_in   = (const float*)d_in[1];
    const float* conv_w = (const float*)d_in[2];
    const float* conv_b = (const float*)d_in[3];
    const float* dt_b   = (const float*)d_in[4];
    const float* A_log  = (const float*)d_in[5];
    const float* Dv     = (const float*)d_in[6];
    const float* norm_w = (const float*)d_in[7];
    const float* W_out  = (const float*)d_in[8];
    float* out = (float*)d_out;

    float *zx = nullptr, *ybuf = nullptr;
    cudaGetSymbolAddress((void**)&zx, g_zx);
    cudaGetSymbolAddress((void**)&ybuf, g_y);
    __nv_bfloat16 *a1h, *a1l, *b1h, *b1l, *a2h, *a2l, *b2h, *b2l;
    cudaGetSymbolAddress((void**)&a1h, g_a1h);
    cudaGetSymbolAddress((void**)&a1l, g_a1l);
    cudaGetSymbolAddress((void**)&b1h, g_b1h);
    cudaGetSymbolAddress((void**)&b1l, g_b1l);
    cudaGetSymbolAddress((void**)&a2h, g_a2h);
    cudaGetSymbolAddress((void**)&a2l, g_a2l);
    cudaGetSymbolAddress((void**)&b2h, g_b2h);
    cudaGetSymbolAddress((void**)&b2l, g_b2l);

    const size_t gemm_smem = 2 * 4 * 16384;  // 131072
    const size_t diag_smem = (size_t)(2 * 64 * 129 + 2 * 64 * 65 + 128) * sizeof(float);
    const size_t yoff_smem = (size_t)(2 * 64 * 129 + 64) * sizeof(float);
    cudaFuncSetAttribute(hmma_gemm_kernel, cudaFuncAttributeMaxDynamicSharedMemorySize, (int)gemm_smem);
    cudaFuncSetAttribute(ssd_diag_kernel, cudaFuncAttributeMaxDynamicSharedMemorySize, (int)diag_smem);
    cudaFuncSetAttribute(yoff_kernel, cudaFuncAttributeMaxDynamicSharedMemorySize, (int)yoff_smem);

    // --- GEMM1 inputs: split u, transpose+split W_in ---
    cvt_split_kernel<<<(MROWS * DMODEL / 4 + 255) / 256, 256>>>(u, a1h, a1l, MROWS * DMODEL / 4);
    transpose_split_kernel<<<dim3(NPAD1 / 32, DMODEL / 32), dim3(32, 32)>>>(W_in, b1h, b1l, DMODEL, DPROJ);

    // --- GEMM1: zx[8192,4384] = u @ W_in (tensor cores) ---
    hmma_gemm_kernel<<<dim3(NPAD1 / 128, MROWS / 128), 256, gemm_smem>>>(
        a1h, a1l, b1h, b1l, zx, DPROJ, DMODEL, DPROJ);

    dt_kernel<<<MROWS * NH / 256, 256>>>(dt_b);
    acum_kernel<<<BQ * NC * NH / 256, 256>>>(A_log);
    conv_kernel<<<dim3(CONVCH / 256, MROWS), 256>>>(conv_w, conv_b);
    ssd_diag_kernel<<<BQ * NC * NH, 256, diag_smem>>>();
    scan_kernel<<<(BQ * NH * HD * DSTATE) / 256, 256>>>();
    yoff_kernel<<<BQ * NC * NH, 256, yoff_smem>>>(Dv);
    gate_kernel<<<MROWS, 256>>>(norm_w);

    // --- GEMM2 inputs: split y, transpose+split W_out ---
    cvt_split_kernel<<<(MROWS * DINNER / 4 + 255) / 256, 256>>>(ybuf, a2h, a2l, MROWS * DINNER / 4);
    transpose_split_kernel<<<dim3(DMODEL / 32, DINNER / 32), dim3(32, 32)>>>(W_out, b2h, b2l, DINNER, DMODEL);

    // --- GEMM2: out[8192,1024] = y @ W_out (tensor cores) ---
    hmma_gemm_kernel<<<dim3(DMODEL / 128, MROWS / 128), 256, gemm_smem>>>(
        a2h, a2l, b2h, b2l, out, DMODEL, DINNER, DMODEL);
}

// round 5
// speedup vs baseline: 2.1816x; 1.4277x over previous
#include <cuda_runtime.h>
#include <cuda_bf16.h>
#include <math.h>
#include <cstdint>

// ---------------- problem constants ----------------
#define BQ 2
#define LSEQ 4096
#define DMODEL 1024
#define DINNER 2048
#define NH 32
#define HD 64
#define DSTATE 128
#define CHK 64
#define NC 64
#define DPROJ 4384
#define CONVCH 2304
#define MROWS (BQ*LSEQ)
#define NPAD1 4480      // DPROJ padded to 128

// ---------------- scratch (device globals; no allocation) ----------------
__device__ float g_zx[(size_t)MROWS * DPROJ];
__device__ float g_xbc[(size_t)MROWS * CONVCH];
__device__ float g_dt[MROWS * NH];
__device__ float g_acum[BQ * NC * NH * CHK];
__device__ float g_suma[BQ * NC * NH];              // exp(sum A*dt) per chunk
__device__ float g_states[(size_t)BQ * NC * NH * HD * DSTATE];
__device__ float g_y[(size_t)MROWS * DINNER];

// bf16 split buffers for tensor-core GEMMs
__device__ __nv_bfloat16 g_a1h[(size_t)MROWS * DMODEL];
__device__ __nv_bfloat16 g_a1l[(size_t)MROWS * DMODEL];
__device__ __nv_bfloat16 g_b1h[(size_t)NPAD1 * DMODEL];
__device__ __nv_bfloat16 g_b1l[(size_t)NPAD1 * DMODEL];
__device__ __nv_bfloat16 g_a2h[(size_t)MROWS * DINNER];
__device__ __nv_bfloat16 g_a2l[(size_t)MROWS * DINNER];
__device__ __nv_bfloat16 g_b2h[(size_t)DMODEL * DINNER];
__device__ __nv_bfloat16 g_b2l[(size_t)DMODEL * DINNER];

// ---------------- PTX helpers (base ISA only) ----------------
__device__ __forceinline__ uint32_t smem_u32(const void* p) {
    uint32_t a;
    asm("{ .reg .u64 t; cvta.to.shared.u64 t, %1; cvt.u32.u64 %0, t; }" : "=r"(a) : "l"(p));
    return a;
}
#define SMEM_SWIZZLE_128B(byte_offset) ((byte_offset) ^ (((byte_offset) >> 3) & 0x70))
#define CP_ASYNC16(dst, src) \
    asm volatile("cp.async.cg.shared.global [%0], [%1], 16;" :: "r"(dst), "l"(src) : "memory")
#define CP_COMMIT() asm volatile("cp.async.commit_group;" ::: "memory")
#define CP_WAIT0()  asm volatile("cp.async.wait_group 0;" ::: "memory")
#define CP_WAIT1()  asm volatile("cp.async.wait_group 1;" ::: "memory")

#define LDSM_X4(r0,r1,r2,r3,addr) \
    asm volatile("ldmatrix.sync.aligned.m8n8.x4.shared.b16 {%0,%1,%2,%3}, [%4];" \
        : "=r"(r0), "=r"(r1), "=r"(r2), "=r"(r3) : "r"(addr))

#define MMA16816(d, a, b0, b1) \
    asm volatile("mma.sync.aligned.m16n8k16.row.col.f32.bf16.bf16.f32 " \
        "{%0,%1,%2,%3}, {%4,%5,%6,%7}, {%8,%9}, {%0,%1,%2,%3};" \
        : "+f"((d)[0]), "+f"((d)[1]), "+f"((d)[2]), "+f"((d)[3]) \
        : "r"((a)[0]), "r"((a)[1]), "r"((a)[2]), "r"((a)[3]), "r"(b0), "r"(b1))

__device__ __forceinline__ void ldsmA(uint32_t base, int row128, int ks, int lane, uint32_t* r) {
    int row = row128 + (lane & 15);
    int off = row * 128 + ks * 32 + ((lane >> 4) << 4);
    LDSM_X4(r[0], r[1], r[2], r[3], base + SMEM_SWIZZLE_128B((uint32_t)off));
}
// NON-trans: Bt stored [n][k] k-contiguous gives col-major B frags.
__device__ __forceinline__ void ldsmB(uint32_t base, int nrow, int ks, int lane, uint32_t* r) {
    int n = nrow + ((lane >> 4) << 3) + (lane & 7);
    int off = n * 128 + ks * 32 + (((lane >> 3) & 1) << 4);
    LDSM_X4(r[0], r[1], r[2], r[3], base + SMEM_SWIZZLE_128B((uint32_t)off));
}

// ---------------- HMMA split-bf16 GEMM: C[M,N] = A[M,K] @ Bt[N,K]^T ----------------
// CTA 128x128, K-chunk 64 bf16, 3-stage cp.async ring, 8 warps of 64x32.
__global__ __launch_bounds__(256, 1) void hmma_gemm_kernel(
    const __nv_bfloat16* __restrict__ Ah, const __nv_bfloat16* __restrict__ Al,
    const __nv_bfloat16* __restrict__ Bh, const __nv_bfloat16* __restrict__ Bl,
    float* __restrict__ C, int N, int K, int ldc)
{
    extern __shared__ char smem[];
    const uint32_t sb = smem_u32(smem);
    const int tid = threadIdx.x, wid = tid >> 5, lane = tid & 31;
    const int wr = wid & 1, wc = wid >> 1;
    const int rowbase = blockIdx.y * 128, colbase = blockIdx.x * 128;
    const int KC = K >> 6;

    float acc[4][4][4];
#pragma unroll
    for (int mi = 0; mi < 4; mi++)
#pragma unroll
        for (int ni = 0; ni < 4; ni++)
#pragma unroll
            for (int j = 0; j < 4; j++) acc[mi][ni][j] = 0.f;

    auto issue_chunk = [&](int i) {
        const uint32_t sbase = (uint32_t)(i % 3) * 65536u;
        const int k0 = i << 6;
#pragma unroll
        for (int v = 0; v < 16; v++) {
            const int buf = v >> 2;                 // 0:Ah 1:Al 2:Bh 3:Bl
            const int idx = ((v & 3) << 8) + tid;
            const int r = idx >> 3, c8 = idx & 7;
            const __nv_bfloat16* src;
            if (buf == 0)      src = Ah + (size_t)(rowbase + r) * K + k0 + c8 * 8;
            else if (buf == 1) src = Al + (size_t)(rowbase + r) * K + k0 + c8 * 8;
            else if (buf == 2) src = Bh + (size_t)(colbase + r) * K + k0 + c8 * 8;
            else               src = Bl + (size_t)(colbase + r) * K + k0 + c8 * 8;
            uint32_t dst = sb + sbase + (uint32_t)buf * 16384u +
                           SMEM_SWIZZLE_128B((uint32_t)(r * 128 + c8 * 16));
            CP_ASYNC16(dst, src);
        }
    };

    issue_chunk(0); CP_COMMIT();
    issue_chunk(1); CP_COMMIT();

    for (int i = 0; i < KC; i++) {
        if (i == KC - 1) { CP_WAIT0(); } else { CP_WAIT1(); }
        __syncthreads();
        if (i + 2 < KC) { issue_chunk(i + 2); CP_COMMIT(); }

        const uint32_t sbase = sb + (uint32_t)(i % 3) * 65536u;
        const uint32_t aH = sbase, aL = sbase + 16384u, bH = sbase + 32768u, bL = sbase + 49152u;
#pragma unroll
        for (int ks = 0; ks < 4; ks++) {
            uint32_t ah[4][4], al[4][4], bh[2][4], bl[2][4];
#pragma unroll
            for (int mi = 0; mi < 4; mi++) {
                ldsmA(aH, wr * 64 + mi * 16, ks, lane, ah[mi]);
                ldsmA(aL, wr * 64 + mi * 16, ks, lane, al[mi]);
            }
#pragma unroll
            for (int np = 0; np < 2; np++) {
                ldsmB(bH, wc * 32 + np * 16, ks, lane, bh[np]);
                ldsmB(bL, wc * 32 + np * 16, ks, lane, bl[np]);
            }
#pragma unroll
            for (int mi = 0; mi < 4; mi++)
#pragma unroll
                for (int ni = 0; ni < 4; ni++) {
                    const int np = ni >> 1, o = (ni & 1) << 1;
                    MMA16816(acc[mi][ni], ah[mi], bh[np][o], bh[np][o + 1]);
                    MMA16816(acc[mi][ni], ah[mi], bl[np][o], bl[np][o + 1]);
                    MMA16816(acc[mi][ni], al[mi], bh[np][o], bh[np][o + 1]);
                }
        }
    }

#pragma unroll
    for (int mi = 0; mi < 4; mi++) {
        const int row = rowbase + wr * 64 + mi * 16 + (lane >> 2);
#pragma unroll
        for (int ni = 0; ni < 4; ni++) {
            const int col = colbase + wc * 32 + ni * 8 + (lane & 3) * 2;
            if (col < N) {
                *reinterpret_cast<float2*>(&C[(size_t)row * ldc + col]) =
                    make_float2(acc[mi][ni][0], acc[mi][ni][1]);
                *reinterpret_cast<float2*>(&C[(size_t)(row + 8) * ldc + col]) =
                    make_float2(acc[mi][ni][2], acc[mi][ni][3]);
            }
        }
    }
}

// ---------------- fp32 -> (hi, lo) bf16 split ----------------
__global__ void cvt_split_kernel(const float* __restrict__ X, __nv_bfloat16* __restrict__ hi,
                                 __nv_bfloat16* __restrict__ lo, int n4) {
    int i = blockIdx.x * blockDim.x + threadIdx.x;
    if (i >= n4) return;
    float4 x = reinterpret_cast<const float4*>(X)[i];
    float xs[4] = {x.x, x.y, x.z, x.w};
    __nv_bfloat16 h[4], l[4];
#pragma unroll
    for (int j = 0; j < 4; j++) {
        h[j] = __float2bfloat16(xs[j]);
        l[j] = __float2bfloat16(xs[j] - __bfloat162float(h[j]));
    }
    reinterpret_cast<__nv_bfloat162*>(hi)[2 * i]     = __nv_bfloat162(h[0], h[1]);
    reinterpret_cast<__nv_bfloat162*>(hi)[2 * i + 1] = __nv_bfloat162(h[2], h[3]);
    reinterpret_cast<__nv_bfloat162*>(lo)[2 * i]     = __nv_bfloat162(l[0], l[1]);
    reinterpret_cast<__nv_bfloat162*>(lo)[2 * i + 1] = __nv_bfloat162(l[2], l[3]);
}

// ---------------- W[K,N] -> Bt[Npad,K] (hi,lo), zero-padded ----------------
__global__ void transpose_split_kernel(const float* __restrict__ W,
                                       __nv_bfloat16* __restrict__ th,
                                       __nv_bfloat16* __restrict__ tl, int K, int N) {
    __shared__ float t[32][33];
    int n = blockIdx.x * 32 + threadIdx.x;
    int k = blockIdx.y * 32 + threadIdx.y;
    t[threadIdx.y][threadIdx.x] = (n < N) ? W[(size_t)k * N + n] : 0.f;
    __syncthreads();
    int nn = blockIdx.x * 32 + threadIdx.y;
    int kk = blockIdx.y * 32 + threadIdx.x;
    float v = t[threadIdx.x][threadIdx.y];
    __nv_bfloat16 h = __float2bfloat16(v);
    th[(size_t)nn * K + kk] = h;
    tl[(size_t)nn * K + kk] = __float2bfloat16(v - __bfloat162float(h));
}

// ---------------- dt = softplus(raw + bias) ----------------
__global__ void dt_kernel(const float* __restrict__ dt_bias) {
    int idx = blockIdx.x * blockDim.x + threadIdx.x;
    int h = idx & 31;
    int m = idx >> 5;
    float x = g_zx[(size_t)m * DPROJ + (DPROJ - NH) + h] + dt_bias[h];
    g_dt[idx] = (x > 20.f) ? x : log1pf(expf(x));
}

// ---------------- per (b,c,h): cumsum of A*dt over chunk ----------------
__global__ void acum_kernel(const float* __restrict__ A_log) {
    int idx = blockIdx.x * blockDim.x + threadIdx.x;
    if (idx >= BQ * NC * NH) return;
    int h = idx & 31;
    int c = (idx >> 5) & 63;
    int b = idx >> 11;
    float A = -expf(A_log[h]);
    int m0 = b * LSEQ + c * CHK;
    float cum = 0.f;
    for (int l = 0; l < CHK; l++) {
        cum += A * g_dt[(m0 + l) * NH + h];
        g_acum[idx * CHK + l] = cum;
    }
    g_suma[idx] = expf(cum);
}

// ---------------- depthwise causal conv(4) + bias + SiLU ----------------
__global__ void conv_kernel(const float* __restrict__ cw, const float* __restrict__ cb) {
    int ch = blockIdx.x * blockDim.x + threadIdx.x;
    int m = blockIdx.y;
    if (ch >= CONVCH) return;
    int l = m & (LSEQ - 1);
    float acc = cb[ch];
#pragma unroll
    for (int k = 0; k < 4; k++) {
        int l2 = l - 3 + k;
        if (l2 >= 0)
            acc = fmaf(g_zx[(size_t)(m - 3 + k) * DPROJ + DINNER + ch], cw[ch * 4 + k], acc);
    }
    g_xbc[(size_t)m * CONVCH + ch] = acc / (1.f + expf(-acc));
}

// ---------------- SSD intra-chunk: Y_diag + local states (register-tiled) ----------------
// smem strides: Bs 129 (scalar reads), Cs 132 (float4), xs/Gs 68 (float4 rows)
#define BS_STR 129
#define CS_STR 132
#define XS_STR 68
__global__ __launch_bounds__(256, 1) void ssd_diag_kernel() {
    int blk = blockIdx.x;
    int h = blk & 31;
    int c = (blk >> 5) & 63;
    int b = blk >> 11;
    int m0 = b * LSEQ + c * CHK;

    extern __shared__ float sm[];
    float* Bs = sm;                        // 64*129
    float* Cs = Bs + 64 * BS_STR;          // 64*132
    float* xs = Cs + 64 * CS_STR;          // 64*68
    float* Gs = xs + 64 * XS_STR;          // 64*68
    float* ac = Gs + 64 * XS_STR;          // 64
    float* wd = ac + 64;                   // 64
    int tid = threadIdx.x;

    // load B (scalar, stride 129), C (float4, stride 132), x*dt (float4, stride 68)
    for (int i = tid; i < 64 * 128; i += 256) {
        int l = i >> 7, n = i & 127;
        Bs[l * BS_STR + n] = g_xbc[(size_t)(m0 + l) * CONVCH + DINNER + n];
    }
    for (int i = tid; i < 64 * 32; i += 256) {
        int l = i >> 5, q = i & 31;
        float4 v = *reinterpret_cast<const float4*>(
            g_xbc + (size_t)(m0 + l) * CONVCH + DINNER + DSTATE + 4 * q);
        *reinterpret_cast<float4*>(Cs + l * CS_STR + 4 * q) = v;
    }
    for (int i = tid; i < 64 * 16; i += 256) {
        int l = i >> 4, q = i & 15;
        float dtv = g_dt[(m0 + l) * NH + h];
        float4 v = *reinterpret_cast<const float4*>(
            g_xbc + (size_t)(m0 + l) * CONVCH + h * HD + 4 * q);
        v.x *= dtv; v.y *= dtv; v.z *= dtv; v.w *= dtv;
        *reinterpret_cast<float4*>(xs + l * XS_STR + 4 * q) = v;
    }
    if (tid < 64) ac[tid] = g_acum[blk * CHK + tid];
    __syncthreads();
    if (tid < 64) wd[tid] = expf(ac[63] - ac[tid]);

    const int tr = tid >> 4, tc = tid & 15;
    const int r0 = tr * 4, c0 = tc * 4;

    // --- G[l][s] = C[l]·B[s], 4x4 per thread ---
    {
        float acc[4][4] = {};
        for (int n = 0; n < 128; n += 4) {
            float4 cr[4];
#pragma unroll
            for (int i = 0; i < 4; i++)
                cr[i] = *reinterpret_cast<const float4*>(Cs + (r0 + i) * CS_STR + n);
#pragma unroll
            for (int nn = 0; nn < 4; nn++) {
                float bv[4];
#pragma unroll
                for (int j = 0; j < 4; j++) bv[j] = Bs[(c0 + j) * BS_STR + n + nn];
                const float ci[4] = {cr[0].x, cr[1].x, cr[2].x, cr[3].x};
                const float c2[4] = {(&cr[0].x)[nn], (&cr[1].x)[nn], (&cr[2].x)[nn], (&cr[3].x)[nn]};
                (void)ci;
#pragma unroll
                for (int i = 0; i < 4; i++)
#pragma unroll
                    for (int j = 0; j < 4; j++) acc[i][j] = fmaf(c2[i], bv[j], acc[i][j]);
            }
        }
#pragma unroll
        for (int i = 0; i < 4; i++) {
            int l = r0 + i;
            float al = ac[l];
            float4 o;
            float* op = &o.x;
#pragma unroll
            for (int j = 0; j < 4; j++) {
                int s = c0 + j;
                op[j] = (s <= l) ? acc[i][j] * expf(al - ac[s]) : 0.f;
            }
            *reinterpret_cast<float4*>(Gs + l * XS_STR + c0) = o;
        }
    }
    __syncthreads();

    // --- Y_diag[l][p] = sum_s G[l][s]*x[s][p], 4x4 per thread ---
    {
        float acc[4][4] = {};
        for (int s = 0; s < 64; s += 4) {
            float4 gr[4];
#pragma unroll
            for (int i = 0; i < 4; i++)
                gr[i] = *reinterpret_cast<const float4*>(Gs + (r0 + i) * XS_STR + s);
#pragma unroll
            for (int ss = 0; ss < 4; ss++) {
                float xv[4];
#pragma unroll
                for (int j = 0; j < 4; j++) xv[j] = xs[(s + ss) * XS_STR + c0 + j];
                const float gi[4] = {(&gr[0].x)[ss], (&gr[1].x)[ss], (&gr[2].x)[ss], (&gr[3].x)[ss]};
#pragma unroll
                for (int i = 0; i < 4; i++)
#pragma unroll
                    for (int j = 0; j < 4; j++) acc[i][j] = fmaf(gi[i], xv[j], acc[i][j]);
            }
        }
#pragma unroll
        for (int i = 0; i < 4; i++) {
            *reinterpret_cast<float4*>(g_y + (size_t)(m0 + r0 + i) * DINNER + h * HD + c0) =
                make_float4(acc[i][0], acc[i][1], acc[i][2], acc[i][3]);
        }
    }

    // --- states S[p][n] = sum_l wd[l]*x[l][p]*B[l][n], 4p x 8n per thread ---
    {
        const int pr = tid & 15, ncq = tid >> 4;   // p0 = 4*pr, n0 = 8*ncq
        const int p0 = pr * 4, n0 = ncq * 8;
        float acc[4][8] = {};
        for (int l = 0; l < 64; l++) {
            float w = wd[l];
            float4 xv = *reinterpret_cast<const float4*>(xs + l * XS_STR + p0);
            float t0 = w * xv.x, t1 = w * xv.y, t2 = w * xv.z, t3 = w * xv.w;
#pragma unroll
            for (int j = 0; j < 8; j++) {
                float bv = Bs[l * BS_STR + n0 + j];
                acc[0][j] = fmaf(t0, bv, acc[0][j]);
                acc[1][j] = fmaf(t1, bv, acc[1][j]);
                acc[2][j] = fmaf(t2, bv, acc[2][j]);
                acc[3][j] = fmaf(t3, bv, acc[3][j]);
            }
        }
#pragma unroll
        for (int i = 0; i < 4; i++) {
            float* dst = g_states + ((size_t)blk * HD + p0 + i) * DSTATE + n0;
            *reinterpret_cast<float4*>(dst)     = make_float4(acc[i][0], acc[i][1], acc[i][2], acc[i][3]);
            *reinterpret_cast<float4*>(dst + 4) = make_float4(acc[i][4], acc[i][5], acc[i][6], acc[i][7]);
        }
    }
}

// ---------------- inter-chunk scan ----------------
__global__ void scan_kernel() {
    int idx = blockIdx.x * blockDim.x + threadIdx.x;
    int n = idx & 127;
    int p = (idx >> 7) & 63;
    int h = (idx >> 13) & 31;
    int b = idx >> 18;
    float prev = 0.f;
    for (int c = 0; c < NC; c++) {
        int bch = (b * NC + c) * NH + h;
        size_t off = ((size_t)bch * HD + p) * DSTATE + n;
        float loc = g_states[off];
        g_states[off] = prev;
        prev = fmaf(prev, g_suma[bch], loc);
    }
}

// ---------------- Y_off + skip: y += exp(ac[l])*(C·P) + x*D (register-tiled) ----------------
__global__ __launch_bounds__(256, 1) void yoff_kernel(const float* __restrict__ Dv) {
    int blk = blockIdx.x;
    int h = blk & 31;
    int c = (blk >> 5) & 63;
    int b = blk >> 11;
    int m0 = b * LSEQ + c * CHK;

    extern __shared__ float sm[];
    float* Ps = sm;                        // 64*129 (p x n), scalar reads
    float* Cs = Ps + 64 * BS_STR;          // 64*132 (l x n), float4 reads
    float* ac = Cs + 64 * CS_STR;          // 64
    int tid = threadIdx.x;

    for (int i = tid; i < 64 * 32; i += 256) {
        int p = i >> 5, q = i & 31;
        float4 v = *reinterpret_cast<const float4*>(
            g_states + ((size_t)blk * HD + p) * DSTATE + 4 * q);
        float* d = Ps + p * BS_STR + 4 * q;
        d[0] = v.x; d[1] = v.y; d[2] = v.z; d[3] = v.w;
    }
    for (int i = tid; i < 64 * 32; i += 256) {
        int l = i >> 5, q = i & 31;
        float4 v = *reinterpret_cast<const float4*>(
            g_xbc + (size_t)(m0 + l) * CONVCH + DINNER + DSTATE + 4 * q);
        *reinterpret_cast<float4*>(Cs + l * CS_STR + 4 * q) = v;
    }
    if (tid < 64) ac[tid] = g_acum[blk * CHK + tid];
    float Dh = Dv[h];
    __syncthreads();

    const int tr = tid >> 4, tc = tid & 15;
    const int r0 = tr * 4, c0 = tc * 4;   // rows l, cols p
    float acc[4][4] = {};
    for (int n = 0; n < 128; n += 4) {
        float4 cr[4];
#pragma unroll
        for (int i = 0; i < 4; i++)
            cr[i] = *reinterpret_cast<const float4*>(Cs + (r0 + i) * CS_STR + n);
#pragma unroll
        for (int nn = 0; nn < 4; nn++) {
            float pv[4];
#pragma unroll
            for (int j = 0; j < 4; j++) pv[j] = Ps[(c0 + j) * BS_STR + n + nn];
            const float ci[4] = {(&cr[0].x)[nn], (&cr[1].x)[nn], (&cr[2].x)[nn], (&cr[3].x)[nn]};
#pragma unroll
            for (int i = 0; i < 4; i++)
#pragma unroll
                for (int j = 0; j < 4; j++) acc[i][j] = fmaf(ci[i], pv[j], acc[i][j]);
        }
    }
#pragma unroll
    for (int i = 0; i < 4; i++) {
        int l = r0 + i;
        int row = m0 + l;
        float el = expf(ac[l]);
        float4 xv = *reinterpret_cast<const float4*>(
            g_xbc + (size_t)row * CONVCH + h * HD + c0);
        float4* yp = reinterpret_cast<float4*>(g_y + (size_t)row * DINNER + h * HD + c0);
        float4 yv = *yp;
        yv.x += acc[i][0] * el + xv.x * Dh;
        yv.y += acc[i][1] * el + xv.y * Dh;
        yv.z += acc[i][2] * el + xv.z * Dh;
        yv.w += acc[i][3] * el + xv.w * Dh;
        *yp = yv;
    }
}

// ---------------- gate (silu(z)) + RMSNorm ----------------
__global__ void gate_kernel(const float* __restrict__ norm_w) {
    int m = blockIdx.x;
    int tid = threadIdx.x;
    __shared__ float red[256];
    float tv[8];
    float ss = 0.f;
#pragma unroll
    for (int j = 0; j < 8; j++) {
        int i = tid + 256 * j;
        float zv = g_zx[(size_t)m * DPROJ + i];
        float yv = g_y[(size_t)m * DINNER + i];
        float g = yv * (zv / (1.f + expf(-zv)));
        tv[j] = g;
        ss += g * g;
    }
    red[tid] = ss;
    __syncthreads();
    for (int s = 128; s > 0; s >>= 1) {
        if (tid < s) red[tid] += red[tid + s];
        __syncthreads();
    }
    float scale = rsqrtf(red[0] / (float)DINNER + 1e-5f);
#pragma unroll
    for (int j = 0; j < 8; j++) {
        int i = tid + 256 * j;
        g_y[(size_t)m * DINNER + i] = tv[j] * scale * norm_w[i];
    }
}

// ---------------- launch ----------------
extern "C" void kernel_launch(void* const* d_in, const int* in_sizes, int n_in,
                              void* d_out, int out_size) {
    const float* u      = (const float*)d_in[0];
    const float* W_in   = (const float*)d_in[1];
    const float* conv_w = (const float*)d_in[2];
    const float* conv_b = (const float*)d_in[3];
    const float* dt_b   = (const float*)d_in[4];
    const float* A_log  = (const float*)d_in[5];
    const float* Dv     = (const float*)d_in[6];
    const float* norm_w = (const float*)d_in[7];
    const float* W_out  = (const float*)d_in[8];
    float* out = (float*)d_out;

    float *zx = nullptr, *ybuf = nullptr;
    cudaGetSymbolAddress((void**)&zx, g_zx);
    cudaGetSymbolAddress((void**)&ybuf, g_y);
    __nv_bfloat16 *a1h, *a1l, *b1h, *b1l, *a2h, *a2l, *b2h, *b2l;
    cudaGetSymbolAddress((void**)&a1h, g_a1h);
    cudaGetSymbolAddress((void**)&a1l, g_a1l);
    cudaGetSymbolAddress((void**)&b1h, g_b1h);
    cudaGetSymbolAddress((void**)&b1l, g_b1l);
    cudaGetSymbolAddress((void**)&a2h, g_a2h);
    cudaGetSymbolAddress((void**)&a2l, g_a2l);
    cudaGetSymbolAddress((void**)&b2h, g_b2h);
    cudaGetSymbolAddress((void**)&b2l, g_b2l);

    const size_t gemm_smem = 3 * 4 * 16384;  // 196608 (3-stage ring)
    const size_t diag_smem = (size_t)(64 * BS_STR + 64 * CS_STR + 2 * 64 * XS_STR + 128) * sizeof(float);
    const size_t yoff_smem = (size_t)(64 * BS_STR + 64 * CS_STR + 64) * sizeof(float);
    cudaFuncSetAttribute(hmma_gemm_kernel, cudaFuncAttributeMaxDynamicSharedMemorySize, (int)gemm_smem);
    cudaFuncSetAttribute(ssd_diag_kernel, cudaFuncAttributeMaxDynamicSharedMemorySize, (int)diag_smem);
    cudaFuncSetAttribute(yoff_kernel, cudaFuncAttributeMaxDynamicSharedMemorySize, (int)yoff_smem);

    // --- GEMM1 inputs ---
    cvt_split_kernel<<<(MROWS * DMODEL / 4 + 255) / 256, 256>>>(u, a1h, a1l, MROWS * DMODEL / 4);
    transpose_split_kernel<<<dim3(NPAD1 / 32, DMODEL / 32), dim3(32, 32)>>>(W_in, b1h, b1l, DMODEL, DPROJ);

    // --- GEMM1: zx[8192,4384] = u @ W_in ---
    hmma_gemm_kernel<<<dim3(NPAD1 / 128, MROWS / 128), 256, gemm_smem>>>(
        a1h, a1l, b1h, b1l, zx, DPROJ, DMODEL, DPROJ);

    dt_kernel<<<MROWS * NH / 256, 256>>>(dt_b);
    acum_kernel<<<BQ * NC * NH / 256, 256>>>(A_log);
    conv_kernel<<<dim3(CONVCH / 256, MROWS), 256>>>(conv_w, conv_b);
    ssd_diag_kernel<<<BQ * NC * NH, 256, diag_smem>>>();
    scan_kernel<<<(BQ * NH * HD * DSTATE) / 256, 256>>>();
    yoff_kernel<<<BQ * NC * NH, 256, yoff_smem>>>(Dv);
    gate_kernel<<<MROWS, 256>>>(norm_w);

    // --- GEMM2 inputs ---
    cvt_split_kernel<<<(MROWS * DINNER / 4 + 255) / 256, 256>>>(ybuf, a2h, a2l, MROWS * DINNER / 4);
    transpose_split_kernel<<<dim3(DMODEL / 32, DINNER / 32), dim3(32, 32)>>>(W_out, b2h, b2l, DINNER, DMODEL);

    // --- GEMM2: out[8192,1024] = y @ W_out ---
    hmma_gemm_kernel<<<dim3(DMODEL / 128, MROWS / 128), 256, gemm_smem>>>(
        a2h, a2l, b2h, b2l, out, DMODEL, DINNER, DMODEL);
}

// round 6
// speedup vs baseline: 2.2647x; 1.0381x over previous
#include <cuda_runtime.h>
#include <cuda_bf16.h>
#include <math.h>
#include <cstdint>

// ---------------- problem constants ----------------
#define BQ 2
#define LSEQ 4096
#define DMODEL 1024
#define DINNER 2048
#define NH 32
#define HD 64
#define DSTATE 128
#define CHK 64
#define NC 64
#define DPROJ 4384
#define CONVCH 2304
#define MROWS (BQ*LSEQ)
#define NPAD1 4480      // DPROJ padded to 128

// ---------------- scratch (device globals; no allocation) ----------------
__device__ float g_zx[(size_t)MROWS * DPROJ];
__device__ float g_xbc[(size_t)MROWS * CONVCH];
__device__ float g_dt[MROWS * NH];
__device__ float g_acum[BQ * NC * NH * CHK];
__device__ float g_suma[BQ * NC * NH];
__device__ float g_states[(size_t)BQ * NC * NH * HD * DSTATE];
__device__ float g_y[(size_t)MROWS * DINNER];

__device__ __nv_bfloat16 g_a1h[(size_t)MROWS * DMODEL];
__device__ __nv_bfloat16 g_a1l[(size_t)MROWS * DMODEL];
__device__ __nv_bfloat16 g_b1h[(size_t)NPAD1 * DMODEL];
__device__ __nv_bfloat16 g_b1l[(size_t)NPAD1 * DMODEL];
__device__ __nv_bfloat16 g_a2h[(size_t)MROWS * DINNER];
__device__ __nv_bfloat16 g_a2l[(size_t)MROWS * DINNER];
__device__ __nv_bfloat16 g_b2h[(size_t)DMODEL * DINNER];
__device__ __nv_bfloat16 g_b2l[(size_t)DMODEL * DINNER];

// ---------------- PTX helpers ----------------
__device__ __forceinline__ uint32_t smem_u32(const void* p) {
    uint32_t a;
    asm("{ .reg .u64 t; cvta.to.shared.u64 t, %1; cvt.u32.u64 %0, t; }" : "=r"(a) : "l"(p));
    return a;
}
#define SMEM_SWIZZLE_128B(byte_offset) ((byte_offset) ^ (((byte_offset) >> 3) & 0x70))
#define CP_ASYNC16(dst, src) \
    asm volatile("cp.async.cg.shared.global [%0], [%1], 16;" :: "r"(dst), "l"(src) : "memory")
#define CP_COMMIT() asm volatile("cp.async.commit_group;" ::: "memory")
#define CP_WAIT0()  asm volatile("cp.async.wait_group 0;" ::: "memory")
#define CP_WAIT1()  asm volatile("cp.async.wait_group 1;" ::: "memory")

#define LDSM_X4(r0,r1,r2,r3,addr) \
    asm volatile("ldmatrix.sync.aligned.m8n8.x4.shared.b16 {%0,%1,%2,%3}, [%4];" \
        : "=r"(r0), "=r"(r1), "=r"(r2), "=r"(r3) : "r"(addr))

#define MMA16816(d, a, b0, b1) \
    asm volatile("mma.sync.aligned.m16n8k16.row.col.f32.bf16.bf16.f32 " \
        "{%0,%1,%2,%3}, {%4,%5,%6,%7}, {%8,%9}, {%0,%1,%2,%3};" \
        : "+f"((d)[0]), "+f"((d)[1]), "+f"((d)[2]), "+f"((d)[3]) \
        : "r"((a)[0]), "r"((a)[1]), "r"((a)[2]), "r"((a)[3]), "r"(b0), "r"(b1))

// packed f32x2 (Blackwell base ISA; 2x fp32 FMA rate)
#define FMA2(d, a, b) asm("fma.rn.f32x2 %0, %1, %2, %0;" : "+l"(d) : "l"(a), "l"(b))
#define MUL2(d, a, b) asm("mul.rn.f32x2 %0, %1, %2;" : "=l"(d) : "l"(a), "l"(b))
__device__ __forceinline__ uint64_t dup2(float x) {
    uint64_t r; asm("mov.b64 %0, {%1, %1};" : "=l"(r) : "f"(x)); return r;
}
__device__ __forceinline__ void up2(uint64_t v, float& lo, float& hi) {
    asm("mov.b64 {%0, %1}, %2;" : "=f"(lo), "=f"(hi) : "l"(v));
}

__device__ __forceinline__ void ldsmA(uint32_t base, int row128, int ks, int lane, uint32_t* r) {
    int row = row128 + (lane & 15);
    int off = row * 128 + ks * 32 + ((lane >> 4) << 4);
    LDSM_X4(r[0], r[1], r[2], r[3], base + SMEM_SWIZZLE_128B((uint32_t)off));
}
__device__ __forceinline__ void ldsmB(uint32_t base, int nrow, int ks, int lane, uint32_t* r) {
    int n = nrow + ((lane >> 4) << 3) + (lane & 7);
    int off = n * 128 + ks * 32 + (((lane >> 3) & 1) << 4);
    LDSM_X4(r[0], r[1], r[2], r[3], base + SMEM_SWIZZLE_128B((uint32_t)off));
}

// ---------------- HMMA split-bf16 GEMM (unchanged from R5) ----------------
__global__ __launch_bounds__(256, 1) void hmma_gemm_kernel(
    const __nv_bfloat16* __restrict__ Ah, const __nv_bfloat16* __restrict__ Al,
    const __nv_bfloat16* __restrict__ Bh, const __nv_bfloat16* __restrict__ Bl,
    float* __restrict__ C, int N, int K, int ldc)
{
    extern __shared__ char smem[];
    const uint32_t sb = smem_u32(smem);
    const int tid = threadIdx.x, wid = tid >> 5, lane = tid & 31;
    const int wr = wid & 1, wc = wid >> 1;
    const int rowbase = blockIdx.y * 128, colbase = blockIdx.x * 128;
    const int KC = K >> 6;

    float acc[4][4][4];
#pragma unroll
    for (int mi = 0; mi < 4; mi++)
#pragma unroll
        for (int ni = 0; ni < 4; ni++)
#pragma unroll
            for (int j = 0; j < 4; j++) acc[mi][ni][j] = 0.f;

    auto issue_chunk = [&](int i) {
        const uint32_t sbase = (uint32_t)(i % 3) * 65536u;
        const int k0 = i << 6;
#pragma unroll
        for (int v = 0; v < 16; v++) {
            const int buf = v >> 2;
            const int idx = ((v & 3) << 8) + tid;
            const int r = idx >> 3, c8 = idx & 7;
            const __nv_bfloat16* src;
            if (buf == 0)      src = Ah + (size_t)(rowbase + r) * K + k0 + c8 * 8;
            else if (buf == 1) src = Al + (size_t)(rowbase + r) * K + k0 + c8 * 8;
            else if (buf == 2) src = Bh + (size_t)(colbase + r) * K + k0 + c8 * 8;
            else               src = Bl + (size_t)(colbase + r) * K + k0 + c8 * 8;
            uint32_t dst = sb + sbase + (uint32_t)buf * 16384u +
                           SMEM_SWIZZLE_128B((uint32_t)(r * 128 + c8 * 16));
            CP_ASYNC16(dst, src);
        }
    };

    issue_chunk(0); CP_COMMIT();
    issue_chunk(1); CP_COMMIT();

    for (int i = 0; i < KC; i++) {
        if (i == KC - 1) { CP_WAIT0(); } else { CP_WAIT1(); }
        __syncthreads();
        if (i + 2 < KC) { issue_chunk(i + 2); CP_COMMIT(); }

        const uint32_t sbase = sb + (uint32_t)(i % 3) * 65536u;
        const uint32_t aH = sbase, aL = sbase + 16384u, bH = sbase + 32768u, bL = sbase + 49152u;
#pragma unroll
        for (int ks = 0; ks < 4; ks++) {
            uint32_t ah[4][4], al[4][4], bh[2][4], bl[2][4];
#pragma unroll
            for (int mi = 0; mi < 4; mi++) {
                ldsmA(aH, wr * 64 + mi * 16, ks, lane, ah[mi]);
                ldsmA(aL, wr * 64 + mi * 16, ks, lane, al[mi]);
            }
#pragma unroll
            for (int np = 0; np < 2; np++) {
                ldsmB(bH, wc * 32 + np * 16, ks, lane, bh[np]);
                ldsmB(bL, wc * 32 + np * 16, ks, lane, bl[np]);
            }
#pragma unroll
            for (int mi = 0; mi < 4; mi++)
#pragma unroll
                for (int ni = 0; ni < 4; ni++) {
                    const int np = ni >> 1, o = (ni & 1) << 1;
                    MMA16816(acc[mi][ni], ah[mi], bh[np][o], bh[np][o + 1]);
                    MMA16816(acc[mi][ni], ah[mi], bl[np][o], bl[np][o + 1]);
                    MMA16816(acc[mi][ni], al[mi], bh[np][o], bh[np][o + 1]);
                }
        }
    }

#pragma unroll
    for (int mi = 0; mi < 4; mi++) {
        const int row = rowbase + wr * 64 + mi * 16 + (lane >> 2);
#pragma unroll
        for (int ni = 0; ni < 4; ni++) {
            const int col = colbase + wc * 32 + ni * 8 + (lane & 3) * 2;
            if (col < N) {
                *reinterpret_cast<float2*>(&C[(size_t)row * ldc + col]) =
                    make_float2(acc[mi][ni][0], acc[mi][ni][1]);
                *reinterpret_cast<float2*>(&C[(size_t)(row + 8) * ldc + col]) =
                    make_float2(acc[mi][ni][2], acc[mi][ni][3]);
            }
        }
    }
}

// ---------------- fp32 -> (hi, lo) bf16 split ----------------
__global__ void cvt_split_kernel(const float* __restrict__ X, __nv_bfloat16* __restrict__ hi,
                                 __nv_bfloat16* __restrict__ lo, int n4) {
    int i = blockIdx.x * blockDim.x + threadIdx.x;
    if (i >= n4) return;
    float4 x = reinterpret_cast<const float4*>(X)[i];
    float xs[4] = {x.x, x.y, x.z, x.w};
    __nv_bfloat16 h[4], l[4];
#pragma unroll
    for (int j = 0; j < 4; j++) {
        h[j] = __float2bfloat16(xs[j]);
        l[j] = __float2bfloat16(xs[j] - __bfloat162float(h[j]));
    }
    reinterpret_cast<__nv_bfloat162*>(hi)[2 * i]     = __nv_bfloat162(h[0], h[1]);
    reinterpret_cast<__nv_bfloat162*>(hi)[2 * i + 1] = __nv_bfloat162(h[2], h[3]);
    reinterpret_cast<__nv_bfloat162*>(lo)[2 * i]     = __nv_bfloat162(l[0], l[1]);
    reinterpret_cast<__nv_bfloat162*>(lo)[2 * i + 1] = __nv_bfloat162(l[2], l[3]);
}

// ---------------- W[K,N] -> Bt[Npad,K] (hi,lo), zero-padded ----------------
__global__ void transpose_split_kernel(const float* __restrict__ W,
                                       __nv_bfloat16* __restrict__ th,
                                       __nv_bfloat16* __restrict__ tl, int K, int N) {
    __shared__ float t[32][33];
    int n = blockIdx.x * 32 + threadIdx.x;
    int k = blockIdx.y * 32 + threadIdx.y;
    t[threadIdx.y][threadIdx.x] = (n < N) ? W[(size_t)k * N + n] : 0.f;
    __syncthreads();
    int nn = blockIdx.x * 32 + threadIdx.y;
    int kk = blockIdx.y * 32 + threadIdx.x;
    float v = t[threadIdx.x][threadIdx.y];
    __nv_bfloat16 h = __float2bfloat16(v);
    th[(size_t)nn * K + kk] = h;
    tl[(size_t)nn * K + kk] = __float2bfloat16(v - __bfloat162float(h));
}

// ---------------- dt = softplus(raw + bias) ----------------
__global__ void dt_kernel(const float* __restrict__ dt_bias) {
    int idx = blockIdx.x * blockDim.x + threadIdx.x;
    int h = idx & 31;
    int m = idx >> 5;
    float x = g_zx[(size_t)m * DPROJ + (DPROJ - NH) + h] + dt_bias[h];
    g_dt[idx] = (x > 20.f) ? x : log1pf(expf(x));
}

// ---------------- per (b,c,h): cumsum of A*dt over chunk ----------------
__global__ void acum_kernel(const float* __restrict__ A_log) {
    int idx = blockIdx.x * blockDim.x + threadIdx.x;
    if (idx >= BQ * NC * NH) return;
    int h = idx & 31;
    int c = (idx >> 5) & 63;
    int b = idx >> 11;
    float A = -expf(A_log[h]);
    int m0 = b * LSEQ + c * CHK;
    float cum = 0.f;
    for (int l = 0; l < CHK; l++) {
        cum += A * g_dt[(m0 + l) * NH + h];
        g_acum[idx * CHK + l] = cum;
    }
    g_suma[idx] = expf(cum);
}

// ---------------- depthwise causal conv(4) + bias + SiLU (smem-tiled) ----------------
// grid: (CONVCH/256, MROWS/16), block 256. 16 rows per block + 3-row halo.
__global__ __launch_bounds__(256) void conv_kernel(const float* __restrict__ cw,
                                                   const float* __restrict__ cb) {
    __shared__ float s[19][256];
    int tid = threadIdx.x;
    int ch = blockIdx.x * 256 + tid;
    int m0 = blockIdx.y * 16;
    int l0 = m0 & (LSEQ - 1);
#pragma unroll
    for (int r = 0; r < 19; r++) {
        int l = l0 - 3 + r;
        s[r][tid] = (l >= 0) ? g_zx[(size_t)(m0 - 3 + r) * DPROJ + DINNER + ch] : 0.f;
    }
    __syncthreads();
    float w0 = cw[ch * 4], w1 = cw[ch * 4 + 1], w2 = cw[ch * 4 + 2], w3 = cw[ch * 4 + 3];
    float bias = cb[ch];
#pragma unroll
    for (int r = 0; r < 16; r++) {
        float acc = bias;
        acc = fmaf(s[r][tid], w0, acc);
        acc = fmaf(s[r + 1][tid], w1, acc);
        acc = fmaf(s[r + 2][tid], w2, acc);
        acc = fmaf(s[r + 3][tid], w3, acc);
        g_xbc[(size_t)(m0 + r) * CONVCH + ch] = acc / (1.f + expf(-acc));
    }
}

// ---------------- SSD intra-chunk: Y_diag + local states (f32x2 + triangular) ----------------
// smem: Bst[n][s] (128 x stride 66), Cs[l][n] (64 x 132), xs[s][p] (64 x 68), Gs[l][s] (64 x 68)
#define TS_STR 66
#define CS_STR 132
#define XS_STR 68
__global__ __launch_bounds__(256, 1) void ssd_diag_kernel() {
    int blk = blockIdx.x;
    int h = blk & 31;
    int c = (blk >> 5) & 63;
    int b = blk >> 11;
    int m0 = b * LSEQ + c * CHK;

    extern __shared__ float sm[];
    float* Bst = sm;                         // 128*66 = 8448
    float* Cs  = Bst + 128 * TS_STR;         // 64*132 = 8448
    float* xs  = Cs + 64 * CS_STR;           // 64*68  = 4352
    float* Gs  = xs + 64 * XS_STR;           // 64*68  = 4352
    float* ac  = Gs + 64 * XS_STR;           // 64
    float* wd  = ac + 64;                    // 64
    int tid = threadIdx.x;

    // B transposed: Bst[n][s]
    for (int i = tid; i < 64 * 128; i += 256) {
        int l = i >> 7, n = i & 127;
        Bst[n * TS_STR + l] = g_xbc[(size_t)(m0 + l) * CONVCH + DINNER + n];
    }
    for (int i = tid; i < 64 * 32; i += 256) {
        int l = i >> 5, q = i & 31;
        float4 v = *reinterpret_cast<const float4*>(
            g_xbc + (size_t)(m0 + l) * CONVCH + DINNER + DSTATE + 4 * q);
        *reinterpret_cast<float4*>(Cs + l * CS_STR + 4 * q) = v;
    }
    for (int i = tid; i < 64 * 16; i += 256) {
        int l = i >> 4, q = i & 15;
        float dtv = g_dt[(m0 + l) * NH + h];
        float4 v = *reinterpret_cast<const float4*>(
            g_xbc + (size_t)(m0 + l) * CONVCH + h * HD + 4 * q);
        v.x *= dtv; v.y *= dtv; v.z *= dtv; v.w *= dtv;
        *reinterpret_cast<float4*>(xs + l * XS_STR + 4 * q) = v;
    }
    if (tid < 64) ac[tid] = g_acum[blk * CHK + tid];
    __syncthreads();
    if (tid < 64) wd[tid] = expf(ac[63] - ac[tid]);

    const int tr = tid >> 4, tc = tid & 15;
    const int r0 = tr * 4, c0 = tc * 4;

    // --- G[l][s] = C[l]·B[s] (only tiles with s<=l can be nonzero) ---
    if (tc <= tr) {
        uint64_t acc2[4][2] = {{0ull,0ull},{0ull,0ull},{0ull,0ull},{0ull,0ull}};
        for (int n4 = 0; n4 < 128; n4 += 4) {
            float4 cr[4];
#pragma unroll
            for (int i = 0; i < 4; i++)
                cr[i] = *reinterpret_cast<const float4*>(Cs + (r0 + i) * CS_STR + n4);
#pragma unroll
            for (int nn = 0; nn < 4; nn++) {
                uint64_t b0 = *reinterpret_cast<const uint64_t*>(Bst + (n4 + nn) * TS_STR + c0);
                uint64_t b1 = *reinterpret_cast<const uint64_t*>(Bst + (n4 + nn) * TS_STR + c0 + 2);
#pragma unroll
                for (int i = 0; i < 4; i++) {
                    uint64_t a2 = dup2((&cr[i].x)[nn]);
                    FMA2(acc2[i][0], a2, b0);
                    FMA2(acc2[i][1], a2, b1);
                }
            }
        }
#pragma unroll
        for (int i = 0; i < 4; i++) {
            int l = r0 + i;
            float al = ac[l];
            float v0, v1, v2, v3;
            up2(acc2[i][0], v0, v1);
            up2(acc2[i][1], v2, v3);
            float4 o;
            o.x = (c0     <= l) ? v0 * expf(al - ac[c0])     : 0.f;
            o.y = (c0 + 1 <= l) ? v1 * expf(al - ac[c0 + 1]) : 0.f;
            o.z = (c0 + 2 <= l) ? v2 * expf(al - ac[c0 + 2]) : 0.f;
            o.w = (c0 + 3 <= l) ? v3 * expf(al - ac[c0 + 3]) : 0.f;
            *reinterpret_cast<float4*>(Gs + l * XS_STR + c0) = o;
        }
    }
    __syncthreads();

    // --- Y_diag[l][p] = sum_{s<=l} G[l][s]*x[s][p] ---
    {
        uint64_t acc2[4][2] = {{0ull,0ull},{0ull,0ull},{0ull,0ull},{0ull,0ull}};
        for (int s4 = 0; s4 < r0 + 4; s4 += 4) {
            float4 gr[4];
#pragma unroll
            for (int i = 0; i < 4; i++)
                gr[i] = *reinterpret_cast<const float4*>(Gs + (r0 + i) * XS_STR + s4);
#pragma unroll
            for (int ss = 0; ss < 4; ss++) {
                uint64_t x0 = *reinterpret_cast<const uint64_t*>(xs + (s4 + ss) * XS_STR + c0);
                uint64_t x1 = *reinterpret_cast<const uint64_t*>(xs + (s4 + ss) * XS_STR + c0 + 2);
#pragma unroll
                for (int i = 0; i < 4; i++) {
                    uint64_t a2 = dup2((&gr[i].x)[ss]);
                    FMA2(acc2[i][0], a2, x0);
                    FMA2(acc2[i][1], a2, x1);
                }
            }
        }
#pragma unroll
        for (int i = 0; i < 4; i++) {
            float v0, v1, v2, v3;
            up2(acc2[i][0], v0, v1);
            up2(acc2[i][1], v2, v3);
            *reinterpret_cast<float4*>(g_y + (size_t)(m0 + r0 + i) * DINNER + h * HD + c0) =
                make_float4(v0, v1, v2, v3);
        }
    }

    // --- states S[p][n] = sum_l wd[l]*x[l][p]*B[l][n] ---
    {
        const int p0 = (tid & 15) * 4, n0 = (tid >> 4) * 8;
        uint64_t acc2[2][8];
#pragma unroll
        for (int pp = 0; pp < 2; pp++)
#pragma unroll
            for (int j = 0; j < 8; j++) acc2[pp][j] = 0ull;
        for (int l = 0; l < 64; l++) {
            uint64_t w2 = dup2(wd[l]);
            uint64_t xa = *reinterpret_cast<const uint64_t*>(xs + l * XS_STR + p0);
            uint64_t xb = *reinterpret_cast<const uint64_t*>(xs + l * XS_STR + p0 + 2);
            uint64_t wxa, wxb;
            MUL2(wxa, xa, w2);
            MUL2(wxb, xb, w2);
#pragma unroll
            for (int j = 0; j < 8; j++) {
                uint64_t b2 = dup2(Bst[(n0 + j) * TS_STR + l]);
                FMA2(acc2[0][j], wxa, b2);
                FMA2(acc2[1][j], wxb, b2);
            }
        }
        float rowv[4][8];
#pragma unroll
        for (int pp = 0; pp < 2; pp++)
#pragma unroll
            for (int j = 0; j < 8; j++)
                up2(acc2[pp][j], rowv[2 * pp][j], rowv[2 * pp + 1][j]);
#pragma unroll
        for (int i = 0; i < 4; i++) {
            float* dst = g_states + ((size_t)blk * HD + p0 + i) * DSTATE + n0;
            *reinterpret_cast<float4*>(dst)     = make_float4(rowv[i][0], rowv[i][1], rowv[i][2], rowv[i][3]);
            *reinterpret_cast<float4*>(dst + 4) = make_float4(rowv[i][4], rowv[i][5], rowv[i][6], rowv[i][7]);
        }
    }
}

// ---------------- inter-chunk scan ----------------
__global__ void scan_kernel() {
    int idx = blockIdx.x * blockDim.x + threadIdx.x;
    int n = idx & 127;
    int p = (idx >> 7) & 63;
    int h = (idx >> 13) & 31;
    int b = idx >> 18;
    float prev = 0.f;
    for (int c = 0; c < NC; c++) {
        int bch = (b * NC + c) * NH + h;
        size_t off = ((size_t)bch * HD + p) * DSTATE + n;
        float loc = g_states[off];
        g_states[off] = prev;
        prev = fmaf(prev, g_suma[bch], loc);
    }
}

// ---------------- Y_off + skip: y += exp(ac[l])*(C·P) + x*D (f32x2) ----------------
__global__ __launch_bounds__(256, 1) void yoff_kernel(const float* __restrict__ Dv) {
    int blk = blockIdx.x;
    int h = blk & 31;
    int c = (blk >> 5) & 63;
    int b = blk >> 11;
    int m0 = b * LSEQ + c * CHK;

    extern __shared__ float sm[];
    float* Pst = sm;                        // [n][p]: 128 x stride 66
    float* Cs  = Pst + 128 * TS_STR;        // [l][n]: 64 x 132
    float* ac  = Cs + 64 * CS_STR;          // 64
    int tid = threadIdx.x;

    for (int i = tid; i < 64 * 128; i += 256) {
        int p = i >> 7, n = i & 127;
        Pst[n * TS_STR + p] = g_states[((size_t)blk * HD + p) * DSTATE + n];
    }
    for (int i = tid; i < 64 * 32; i += 256) {
        int l = i >> 5, q = i & 31;
        float4 v = *reinterpret_cast<const float4*>(
            g_xbc + (size_t)(m0 + l) * CONVCH + DINNER + DSTATE + 4 * q);
        *reinterpret_cast<float4*>(Cs + l * CS_STR + 4 * q) = v;
    }
    if (tid < 64) ac[tid] = g_acum[blk * CHK + tid];
    float Dh = Dv[h];
    __syncthreads();

    const int tr = tid >> 4, tc = tid & 15;
    const int r0 = tr * 4, c0 = tc * 4;   // rows l, cols p
    uint64_t acc2[4][2] = {{0ull,0ull},{0ull,0ull},{0ull,0ull},{0ull,0ull}};
    for (int n4 = 0; n4 < 128; n4 += 4) {
        float4 cr[4];
#pragma unroll
        for (int i = 0; i < 4; i++)
            cr[i] = *reinterpret_cast<const float4*>(Cs + (r0 + i) * CS_STR + n4);
#pragma unroll
        for (int nn = 0; nn < 4; nn++) {
            uint64_t p0v = *reinterpret_cast<const uint64_t*>(Pst + (n4 + nn) * TS_STR + c0);
            uint64_t p1v = *reinterpret_cast<const uint64_t*>(Pst + (n4 + nn) * TS_STR + c0 + 2);
#pragma unroll
            for (int i = 0; i < 4; i++) {
                uint64_t a2 = dup2((&cr[i].x)[nn]);
                FMA2(acc2[i][0], a2, p0v);
                FMA2(acc2[i][1], a2, p1v);
            }
        }
    }
#pragma unroll
    for (int i = 0; i < 4; i++) {
        int l = r0 + i;
        int row = m0 + l;
        float el = expf(ac[l]);
        float v0, v1, v2, v3;
        up2(acc2[i][0], v0, v1);
        up2(acc2[i][1], v2, v3);
        float4 xv = *reinterpret_cast<const float4*>(
            g_xbc + (size_t)row * CONVCH + h * HD + c0);
        float4* yp = reinterpret_cast<float4*>(g_y + (size_t)row * DINNER + h * HD + c0);
        float4 yv = *yp;
        yv.x += v0 * el + xv.x * Dh;
        yv.y += v1 * el + xv.y * Dh;
        yv.z += v2 * el + xv.z * Dh;
        yv.w += v3 * el + xv.w * Dh;
        *yp = yv;
    }
}

// ---------------- gate (silu(z)) + RMSNorm, fused bf16 split output ----------------
__global__ void gate_kernel(const float* __restrict__ norm_w,
                            __nv_bfloat16* __restrict__ a2h, __nv_bfloat16* __restrict__ a2l) {
    int m = blockIdx.x;
    int tid = threadIdx.x;
    __shared__ float red[256];
    float tv[8];
    float ss = 0.f;
#pragma unroll
    for (int j = 0; j < 8; j++) {
        int i = tid + 256 * j;
        float zv = g_zx[(size_t)m * DPROJ + i];
        float yv = g_y[(size_t)m * DINNER + i];
        float g = yv * (zv / (1.f + expf(-zv)));
        tv[j] = g;
        ss += g * g;
    }
    red[tid] = ss;
    __syncthreads();
    for (int s = 128; s > 0; s >>= 1) {
        if (tid < s) red[tid] += red[tid + s];
        __syncthreads();
    }
    float scale = rsqrtf(red[0] / (float)DINNER + 1e-5f);
#pragma unroll
    for (int j = 0; j < 8; j++) {
        int i = tid + 256 * j;
        float val = tv[j] * scale * norm_w[i];
        __nv_bfloat16 hv = __float2bfloat16(val);
        a2h[(size_t)m * DINNER + i] = hv;
        a2l[(size_t)m * DINNER + i] = __float2bfloat16(val - __bfloat162float(hv));
    }
}

// ---------------- launch ----------------
extern "C" void kernel_launch(void* const* d_in, const int* in_sizes, int n_in,
                              void* d_out, int out_size) {
    const float* u      = (const float*)d_in[0];
    const float* W_in   = (const float*)d_in[1];
    const float* conv_w = (const float*)d_in[2];
    const float* conv_b = (const float*)d_in[3];
    const float* dt_b   = (const float*)d_in[4];
    const float* A_log  = (const float*)d_in[5];
    const float* Dv     = (const float*)d_in[6];
    const float* norm_w = (const float*)d_in[7];
    const float* W_out  = (const float*)d_in[8];
    float* out = (float*)d_out;

    float* zx = nullptr;
    cudaGetSymbolAddress((void**)&zx, g_zx);
    __nv_bfloat16 *a1h, *a1l, *b1h, *b1l, *a2h, *a2l, *b2h, *b2l;
    cudaGetSymbolAddress((void**)&a1h, g_a1h);
    cudaGetSymbolAddress((void**)&a1l, g_a1l);
    cudaGetSymbolAddress((void**)&b1h, g_b1h);
    cudaGetSymbolAddress((void**)&b1l, g_b1l);
    cudaGetSymbolAddress((void**)&a2h, g_a2h);
    cudaGetSymbolAddress((void**)&a2l, g_a2l);
    cudaGetSymbolAddress((void**)&b2h, g_b2h);
    cudaGetSymbolAddress((void**)&b2l, g_b2l);

    const size_t gemm_smem = 3 * 4 * 16384;  // 196608
    const size_t diag_smem = (size_t)(128 * TS_STR + 64 * CS_STR + 2 * 64 * XS_STR + 128) * sizeof(float);
    const size_t yoff_smem = (size_t)(128 * TS_STR + 64 * CS_STR + 64) * sizeof(float);
    cudaFuncSetAttribute(hmma_gemm_kernel, cudaFuncAttributeMaxDynamicSharedMemorySize, (int)gemm_smem);
    cudaFuncSetAttribute(ssd_diag_kernel, cudaFuncAttributeMaxDynamicSharedMemorySize, (int)diag_smem);
    cudaFuncSetAttribute(yoff_kernel, cudaFuncAttributeMaxDynamicSharedMemorySize, (int)yoff_smem);

    // --- GEMM1 inputs ---
    cvt_split_kernel<<<(MROWS * DMODEL / 4 + 255) / 256, 256>>>(u, a1h, a1l, MROWS * DMODEL / 4);
    transpose_split_kernel<<<dim3(NPAD1 / 32, DMODEL / 32), dim3(32, 32)>>>(W_in, b1h, b1l, DMODEL, DPROJ);

    // --- GEMM1 ---
    hmma_gemm_kernel<<<dim3(NPAD1 / 128, MROWS / 128), 256, gemm_smem>>>(
        a1h, a1l, b1h, b1l, zx, DPROJ, DMODEL, DPROJ);

    dt_kernel<<<MROWS * NH / 256, 256>>>(dt_b);
    acum_kernel<<<BQ * NC * NH / 256, 256>>>(A_log);
    conv_kernel<<<dim3(CONVCH / 256, MROWS / 16), 256>>>(conv_w, conv_b);
    ssd_diag_kernel<<<BQ * NC * NH, 256, diag_smem>>>();
    scan_kernel<<<(BQ * NH * HD * DSTATE) / 256, 256>>>();
    yoff_kernel<<<BQ * NC * NH, 256, yoff_smem>>>(Dv);
    gate_kernel<<<MROWS, 256>>>(norm_w, a2h, a2l);

    // --- GEMM2 inputs (A fused in gate; only W transpose) ---
    transpose_split_kernel<<<dim3(DMODEL / 32, DINNER / 32), dim3(32, 32)>>>(W_out, b2h, b2l, DINNER, DMODEL);

    // --- GEMM2 ---
    hmma_gemm_kernel<<<dim3(DMODEL / 128, MROWS / 128), 256, gemm_smem>>>(
        a2h, a2l, b2h, b2l, out, DMODEL, DINNER, DMODEL);
}